// round 14
// baseline (speedup 1.0000x reference)
#include <cuda_runtime.h>
#include <cuda_fp16.h>
#include <cstdint>

#define NN 50000
#define EEMAX 800000

// ---------------- scratch (static device globals; no allocation) -------------
__device__ __align__(16) __half g_in0[NN * 128];    // fp16 layer-0 input
__device__ __align__(16) __half g_feat[NN * 256];   // fp16 features
__device__ __align__(16) __half g_out[NN * 256];    // fp16 activated layer output
__device__ __align__(16) __half g_wtf[256 * 128 + 2 * 256 * 256];  // fp16 weights
__device__ float g_ssrc[NN * 4];
__device__ float g_sdst[NN * 4];
__device__ __align__(16) float g_ew[(EEMAX + NN) * 4];  // alpha, then exp weights, per edge
__device__ int   g_deg[NN];
__device__ int   g_cursor[NN];
__device__ int   g_rowptr[NN + 1];
__device__ int   g_csrc[EEMAX + NN];
__device__ int   g_bsum[512];

__device__ __forceinline__ float lrelu(float x, float s) { return x >= 0.f ? x : s * x; }

// fp16 mma with fp32 accumulate: same 10-bit mantissa as tf32-rna (R5/R8 lesson)
__device__ __forceinline__ void mma_f16(float4& c, const uint32_t a[4], const uint32_t b[2]) {
    asm volatile(
        "mma.sync.aligned.m16n8k16.row.col.f32.f16.f16.f32 "
        "{%0,%1,%2,%3}, {%4,%5,%6,%7}, {%8,%9}, {%0,%1,%2,%3};"
        : "+f"(c.x), "+f"(c.y), "+f"(c.z), "+f"(c.w)
        : "r"(a[0]), "r"(a[1]), "r"(a[2]), "r"(a[3]), "r"(b[0]), "r"(b[1]));
}

__device__ __forceinline__ void cp16(uint32_t smem_dst, const void* gsrc, int src_bytes) {
    asm volatile("cp.async.ca.shared.global [%0], [%1], 16, %2;\n"
                 :: "r"(smem_dst), "l"(gsrc), "r"(src_bytes));
}

// ---------------- layer-0 input build (fp16) + fused weight convert ----------
// blocks [0, nBuild): in0 build; blocks [nBuild, nBuild+256): weight convert
__global__ void build_in0_kernel(const float* __restrict__ x,
                                 const int* __restrict__ batch,
                                 const int* __restrict__ clab,
                                 const float* __restrict__ emb,
                                 const float* __restrict__ W0,
                                 const float* __restrict__ W1,
                                 const float* __restrict__ W2,
                                 int n, int nBuild) {
    if (blockIdx.x >= nBuild) {
        int i = (blockIdx.x - nBuild) * blockDim.x + threadIdx.x;
        const int S0 = 256 * 128, S1 = 256 * 256;
        if (i < S0)                 g_wtf[i] = __float2half_rn(W0[i]);
        if (i < S1) {
            g_wtf[S0 + i]      = __float2half_rn(W1[i]);
            g_wtf[S0 + S1 + i] = __float2half_rn(W2[i]);
        }
        return;
    }
    int gt = blockIdx.x * blockDim.x + threadIdx.x;
    int node = gt >> 5, lane = gt & 31;
    if (node >= n) return;
    float4 v;
    if (lane < 16) {
        v = reinterpret_cast<const float4*>(x + (size_t)node * 64)[lane];
    } else {
        int c = clab[batch[node]];
        v = reinterpret_cast<const float4*>(emb + (size_t)c * 64)[lane - 16];
    }
    __half2 h0 = __floats2half2_rn(v.x, v.y);
    __half2 h1 = __floats2half2_rn(v.z, v.w);
    *reinterpret_cast<uint2*>(g_in0 + (size_t)node * 128 + lane * 4) =
        make_uint2(*reinterpret_cast<uint32_t*>(&h0), *reinterpret_cast<uint32_t*>(&h1));
}

// ---------------- tensor-core GEMM + fused attention scores ------------------
// 2-stage cp.async (3-stage proved neutral: R12)
#define SMSH (128 * 40)

template <int K, int SRC>
__global__ void __launch_bounds__(256, 2) gemm_tc_kernel(int woff, int M,
                                                         const float* __restrict__ asrc,
                                                         const float* __restrict__ adst) {
    constexpr int NT = K / 32;
    extern __shared__ __half smh[];
    const __half* __restrict__ A = (SRC == 0) ? g_in0 : g_out;
    const __half* __restrict__ Wm = g_wtf + woff;

    const int tid = threadIdx.x;
    const int warp = tid >> 5, lane = tid & 31;
    const int wm = warp >> 1;
    const int wn = warp & 1;
    const int g = lane >> 2, t4 = lane & 3;
    const int rowBase = blockIdx.x * 128;
    const int colBase = blockIdx.y * 128;

    const uint32_t sbase = (uint32_t)__cvta_generic_to_shared(smh);

    float4 c[2][8];
#pragma unroll
    for (int i = 0; i < 2; i++)
#pragma unroll
        for (int j = 0; j < 8; j++) c[i][j] = make_float4(0.f, 0.f, 0.f, 0.f);

    auto issue = [&](int t) {
        const int buf = t & 1;
        const int k0 = t * 32;
#pragma unroll
        for (int i = 0; i < 2; i++) {
            int f = tid + i * 256;
            int r = f >> 2, cc = (f & 3) * 8;
            int gr = rowBase + r;
            uint32_t da = sbase + (uint32_t)(buf * SMSH + r * 40 + cc) * 2u;
            cp16(da, A + (size_t)gr * K + k0 + cc, (gr < M) ? 16 : 0);
        }
#pragma unroll
        for (int i = 0; i < 2; i++) {
            int f = tid + i * 256;
            int r = f >> 2, cc = (f & 3) * 8;
            uint32_t db = sbase + (uint32_t)((2 + buf) * SMSH + r * 40 + cc) * 2u;
            cp16(db, Wm + (size_t)(colBase + r) * K + k0 + cc, 16);
        }
        asm volatile("cp.async.commit_group;\n" ::);
    };

    issue(0);

#pragma unroll 1
    for (int t = 0; t < NT; t++) {
        if (t + 1 < NT) {
            issue(t + 1);
            asm volatile("cp.async.wait_group 1;\n" ::);
        } else {
            asm volatile("cp.async.wait_group 0;\n" ::);
        }
        __syncthreads();
        const int buf = t & 1;
        const __half* Ab = smh + buf * SMSH;
        const __half* Bb = smh + (2 + buf) * SMSH;
#pragma unroll
        for (int ks = 0; ks < 2; ks++) {
            const int kb = ks * 16 + t4 * 2;
            uint32_t bfr[8][2];
#pragma unroll
            for (int j = 0; j < 8; j++) {
                int cn = wn * 64 + j * 8 + g;
                bfr[j][0] = *reinterpret_cast<const uint32_t*>(&Bb[cn * 40 + kb]);
                bfr[j][1] = *reinterpret_cast<const uint32_t*>(&Bb[cn * 40 + kb + 8]);
            }
            uint32_t afr[2][4];
#pragma unroll
            for (int i = 0; i < 2; i++) {
                int r = wm * 32 + i * 16 + g;
                afr[i][0] = *reinterpret_cast<const uint32_t*>(&Ab[r * 40 + kb]);
                afr[i][1] = *reinterpret_cast<const uint32_t*>(&Ab[(r + 8) * 40 + kb]);
                afr[i][2] = *reinterpret_cast<const uint32_t*>(&Ab[r * 40 + kb + 8]);
                afr[i][3] = *reinterpret_cast<const uint32_t*>(&Ab[(r + 8) * 40 + kb + 8]);
            }
#pragma unroll
            for (int i = 0; i < 2; i++)
#pragma unroll
                for (int j = 0; j < 8; j++) mma_f16(c[i][j], afr[i], bfr[j]);
        }
        __syncthreads();
    }

    // epilogue A: fp16 store to g_feat[M,256]
#pragma unroll
    for (int i = 0; i < 2; i++) {
#pragma unroll
        for (int j = 0; j < 8; j++) {
            int row0 = rowBase + wm * 32 + i * 16 + g;
            int coln = colBase + wn * 64 + j * 8 + 2 * t4;
            if (row0 < M)
                *reinterpret_cast<__half2*>(g_feat + (size_t)row0 * 256 + coln) =
                    __floats2half2_rn(c[i][j].x, c[i][j].y);
            if (row0 + 8 < M)
                *reinterpret_cast<__half2*>(g_feat + (size_t)(row0 + 8) * 256 + coln) =
                    __floats2half2_rn(c[i][j].z, c[i][j].w);
        }
    }

    // epilogue B: fused attention scores (warp's 64 cols == one head)
    {
        const int head = blockIdx.y * 2 + wn;
        const float* ah = asrc + head * 64;
        const float* dh = adst + head * 64;
        float ssp[4] = {0.f, 0.f, 0.f, 0.f}, sdp[4] = {0.f, 0.f, 0.f, 0.f};
#pragma unroll
        for (int j = 0; j < 8; j++) {
            int col = j * 8 + 2 * t4;
            float2 av = *reinterpret_cast<const float2*>(ah + col);
            float2 dv = *reinterpret_cast<const float2*>(dh + col);
#pragma unroll
            for (int i = 0; i < 2; i++) {
                ssp[i * 2]     += c[i][j].x * av.x + c[i][j].y * av.y;
                ssp[i * 2 + 1] += c[i][j].z * av.x + c[i][j].w * av.y;
                sdp[i * 2]     += c[i][j].x * dv.x + c[i][j].y * dv.y;
                sdp[i * 2 + 1] += c[i][j].z * dv.x + c[i][j].w * dv.y;
            }
        }
#pragma unroll
        for (int off = 1; off <= 2; off <<= 1) {
#pragma unroll
            for (int k = 0; k < 4; k++) {
                ssp[k] += __shfl_xor_sync(0xffffffffu, ssp[k], off);
                sdp[k] += __shfl_xor_sync(0xffffffffu, sdp[k], off);
            }
        }
        if (t4 == 0) {
#pragma unroll
            for (int k = 0; k < 4; k++) {
                int row = rowBase + wm * 32 + (k >> 1) * 16 + (k & 1) * 8 + g;
                if (row < M) {
                    g_ssrc[row * 4 + head] = ssp[k];
                    g_sdst[row * 4 + head] = sdp[k];
                }
            }
        }
    }
}

// ---------------- CSR build --------------------------------------------------
// deg: real edges only, 2 per thread via int2; self-loops folded into scan1 (+1)
__global__ void deg_kernel(const int* __restrict__ ei, int E) {
    int t = blockIdx.x * blockDim.x + threadIdx.x;
    int e = t * 2;
    if (e + 1 < E) {
        int2 d2 = *reinterpret_cast<const int2*>(ei + E + e);
        atomicAdd(&g_deg[d2.x], 1);
        atomicAdd(&g_deg[d2.y], 1);
    } else if (e < E) {
        atomicAdd(&g_deg[ei[E + e]], 1);
    }
}

__global__ void scan1_kernel(int n) {
    __shared__ int sh[512];
    int i = blockIdx.x * 512 + threadIdx.x;
    int v = (i < n) ? g_deg[i] + 1 : 0;   // +1 = the node's self-loop
    sh[threadIdx.x] = v;
    __syncthreads();
#pragma unroll
    for (int off = 1; off < 512; off <<= 1) {
        int t = (threadIdx.x >= off) ? sh[threadIdx.x - off] : 0;
        __syncthreads();
        if (threadIdx.x >= off) sh[threadIdx.x] += t;
        __syncthreads();
    }
    if (i < n) g_rowptr[i] = sh[threadIdx.x] - v;
    if (threadIdx.x == 511) g_bsum[blockIdx.x] = sh[511];
}

// merged scan2+scan3: every block redundantly scans the <=512 block sums,
// applies its exclusive prefix, and seeds cursor (R13).
__global__ void scan23_kernel(int nb, int n) {
    __shared__ int sh[512];
    int v = (threadIdx.x < nb) ? g_bsum[threadIdx.x] : 0;
    sh[threadIdx.x] = v;
    __syncthreads();
#pragma unroll
    for (int off = 1; off < 512; off <<= 1) {
        int t = (threadIdx.x >= off) ? sh[threadIdx.x - off] : 0;
        __syncthreads();
        if (threadIdx.x >= off) sh[threadIdx.x] += t;
        __syncthreads();
    }
    int bpre = (blockIdx.x > 0) ? sh[blockIdx.x - 1] : 0;
    int i = blockIdx.x * 512 + threadIdx.x;
    if (i < n) {
        int r = g_rowptr[i] + bpre;
        g_rowptr[i] = r;
        g_cursor[i] = r;
    }
    if (blockIdx.x == 0 && threadIdx.x == 0) g_rowptr[n] = sh[nb - 1];
}

// scatter: threads [0, halfE) do edge pairs; threads [halfE, halfE+n) do self-loops
__global__ void scatter_kernel(const int* __restrict__ ei, int E, int halfE, int n) {
    int t = blockIdx.x * blockDim.x + threadIdx.x;
    if (t < halfE) {
        int e = t * 2;
        if (e + 1 < E) {
            int2 s2v = *reinterpret_cast<const int2*>(ei + e);
            int2 d2  = *reinterpret_cast<const int2*>(ei + E + e);
            g_csrc[atomicAdd(&g_cursor[d2.x], 1)] = s2v.x;
            g_csrc[atomicAdd(&g_cursor[d2.y], 1)] = s2v.y;
        } else {
            g_csrc[atomicAdd(&g_cursor[ei[E + e]], 1)] = ei[e];
        }
    } else {
        int i = t - halfE;
        if (i < n) g_csrc[atomicAdd(&g_cursor[i], 1)] = i;   // self-loop
    }
}

// ---------------- fused softmax + aggregation (+ classifier on last layer) ---
// R10 form: 2-edge unroll (4-edge regressed via register pressure: R11)
template <bool LAST>
__global__ void agg_kernel(const float* __restrict__ b,
                           const float* __restrict__ clsW,
                           const float* __restrict__ clsb,
                           float* __restrict__ y, int n) {
    int gt = blockIdx.x * blockDim.x + threadIdx.x;
    int dst = gt >> 5, lane = gt & 31;
    if (dst >= n) return;
    const int beg = g_rowptr[dst], end = g_rowptr[dst + 1];
    const float4 sd4 = *reinterpret_cast<const float4*>(g_sdst + (size_t)dst * 4);

    // phase 1: segment max per head; cache alpha coalesced into g_ew
    const float NEG = __int_as_float(0xff800000);
    float4 mx = make_float4(NEG, NEG, NEG, NEG);
    for (int i = beg + lane; i < end; i += 32) {
        int s = g_csrc[i];
        float4 ss = *reinterpret_cast<const float4*>(g_ssrc + (size_t)s * 4);
        float4 a;
        a.x = lrelu(ss.x + sd4.x, 0.2f); a.y = lrelu(ss.y + sd4.y, 0.2f);
        a.z = lrelu(ss.z + sd4.z, 0.2f); a.w = lrelu(ss.w + sd4.w, 0.2f);
        reinterpret_cast<float4*>(g_ew)[i] = a;
        mx.x = fmaxf(mx.x, a.x); mx.y = fmaxf(mx.y, a.y);
        mx.z = fmaxf(mx.z, a.z); mx.w = fmaxf(mx.w, a.w);
    }
#pragma unroll
    for (int off = 16; off; off >>= 1) {
        mx.x = fmaxf(mx.x, __shfl_xor_sync(0xffffffffu, mx.x, off));
        mx.y = fmaxf(mx.y, __shfl_xor_sync(0xffffffffu, mx.y, off));
        mx.z = fmaxf(mx.z, __shfl_xor_sync(0xffffffffu, mx.z, off));
        mx.w = fmaxf(mx.w, __shfl_xor_sync(0xffffffffu, mx.w, off));
    }

    // phase 2: exp from cached alpha (coalesced), write back ex, sum denom
    float4 den = make_float4(0.f, 0.f, 0.f, 0.f);
    for (int i = beg + lane; i < end; i += 32) {
        float4 a = reinterpret_cast<const float4*>(g_ew)[i];
        float4 ex;
        ex.x = __expf(a.x - mx.x); ex.y = __expf(a.y - mx.y);
        ex.z = __expf(a.z - mx.z); ex.w = __expf(a.w - mx.w);
        reinterpret_cast<float4*>(g_ew)[i] = ex;
        den.x += ex.x; den.y += ex.y; den.z += ex.z; den.w += ex.w;
    }
#pragma unroll
    for (int off = 16; off; off >>= 1) {
        den.x += __shfl_xor_sync(0xffffffffu, den.x, off);
        den.y += __shfl_xor_sync(0xffffffffu, den.y, off);
        den.z += __shfl_xor_sync(0xffffffffu, den.z, off);
        den.w += __shfl_xor_sync(0xffffffffu, den.w, off);
    }

    const int h = lane >> 3;
    float dh = (h & 2) ? ((h & 1) ? den.w : den.z) : ((h & 1) ? den.y : den.x);
    const float invd = 1.f / (dh + 1e-16f);

    // phase 3: weighted aggregation over fp16 features, 2-edge unroll
    float2 acc[4];
#pragma unroll
    for (int j = 0; j < 4; j++) acc[j] = make_float2(0.f, 0.f);

    int i = beg;
    for (; i + 1 < end; i += 2) {
        int s0 = g_csrc[i], s1 = g_csrc[i + 1];
        float w0 = g_ew[(size_t)i * 4 + h] * invd;
        float w1 = g_ew[(size_t)(i + 1) * 4 + h] * invd;
        uint4 p0 = *reinterpret_cast<const uint4*>(g_feat + (size_t)s0 * 256 + lane * 8);
        uint4 p1 = *reinterpret_cast<const uint4*>(g_feat + (size_t)s1 * 256 + lane * 8);
        const __half2* q0 = reinterpret_cast<const __half2*>(&p0);
        const __half2* q1 = reinterpret_cast<const __half2*>(&p1);
#pragma unroll
        for (int j = 0; j < 4; j++) {
            float2 f0 = __half22float2(q0[j]);
            float2 f1 = __half22float2(q1[j]);
            acc[j].x += w0 * f0.x + w1 * f1.x;
            acc[j].y += w0 * f0.y + w1 * f1.y;
        }
    }
    if (i < end) {
        int s0 = g_csrc[i];
        float w0 = g_ew[(size_t)i * 4 + h] * invd;
        uint4 p0 = *reinterpret_cast<const uint4*>(g_feat + (size_t)s0 * 256 + lane * 8);
        const __half2* q0 = reinterpret_cast<const __half2*>(&p0);
#pragma unroll
        for (int j = 0; j < 4; j++) {
            float2 f0 = __half22float2(q0[j]);
            acc[j].x += w0 * f0.x;
            acc[j].y += w0 * f0.y;
        }
    }

    const float4 b0 = reinterpret_cast<const float4*>(b)[lane * 2];
    const float4 b1 = reinterpret_cast<const float4*>(b)[lane * 2 + 1];
    float o[8];
    o[0] = lrelu(acc[0].x + b0.x, 0.01f); o[1] = lrelu(acc[0].y + b0.y, 0.01f);
    o[2] = lrelu(acc[1].x + b0.z, 0.01f); o[3] = lrelu(acc[1].y + b0.w, 0.01f);
    o[4] = lrelu(acc[2].x + b1.x, 0.01f); o[5] = lrelu(acc[2].y + b1.y, 0.01f);
    o[6] = lrelu(acc[3].x + b1.z, 0.01f); o[7] = lrelu(acc[3].y + b1.w, 0.01f);

    if (!LAST) {
        __half2 h0 = __floats2half2_rn(o[0], o[1]);
        __half2 h1 = __floats2half2_rn(o[2], o[3]);
        __half2 h2 = __floats2half2_rn(o[4], o[5]);
        __half2 h3 = __floats2half2_rn(o[6], o[7]);
        *reinterpret_cast<uint4*>(g_out + (size_t)dst * 256 + lane * 8) =
            make_uint4(*reinterpret_cast<uint32_t*>(&h0), *reinterpret_cast<uint32_t*>(&h1),
                       *reinterpret_cast<uint32_t*>(&h2), *reinterpret_cast<uint32_t*>(&h3));
    } else {
        const float4 w0 = reinterpret_cast<const float4*>(clsW)[lane * 2];
        const float4 w1 = reinterpret_cast<const float4*>(clsW)[lane * 2 + 1];
        float sum = o[0] * w0.x + o[1] * w0.y + o[2] * w0.z + o[3] * w0.w +
                    o[4] * w1.x + o[5] * w1.y + o[6] * w1.z + o[7] * w1.w;
#pragma unroll
        for (int off = 16; off; off >>= 1) sum += __shfl_xor_sync(0xffffffffu, sum, off);
        if (lane == 0) y[dst] = sum + clsb[0];
    }
}

static inline int cdiv(int a, int b) { return (a + b - 1) / b; }

extern "C" void kernel_launch(void* const* d_in, const int* in_sizes, int n_in,
                              void* d_out, int out_size) {
    const float* x     = (const float*)d_in[0];
    const int*   ei    = (const int*)d_in[1];
    const int*   batch = (const int*)d_in[2];
    const int*   clab  = (const int*)d_in[3];
    const float* emb   = (const float*)d_in[4];
    const float* W0    = (const float*)d_in[5];
    const float* as0   = (const float*)d_in[6];
    const float* ad0   = (const float*)d_in[7];
    const float* b0    = (const float*)d_in[8];
    const float* W1    = (const float*)d_in[9];
    const float* as1   = (const float*)d_in[10];
    const float* ad1   = (const float*)d_in[11];
    const float* b1    = (const float*)d_in[12];
    const float* W2    = (const float*)d_in[13];
    const float* as2   = (const float*)d_in[14];
    const float* ad2   = (const float*)d_in[15];
    const float* b2    = (const float*)d_in[16];
    const float* clsW  = (const float*)d_in[17];
    const float* clsb  = (const float*)d_in[18];

    int n  = in_sizes[0] / 64;   // 50000
    int E  = in_sizes[1] / 2;    // 800000
    int halfE = cdiv(E, 2);

    const int T = 256;
    int buildBlocks = cdiv(n * 32, T);
    int aggBlocks = cdiv(n * 32, 128);
    int nb = cdiv(n, 512);
    const int smBytes = 4 * SMSH * sizeof(__half);   // 40960 (2-stage)

    static cudaStream_t s2 = nullptr;
    static cudaEvent_t evFork = nullptr, evJoin = nullptr;
    static void* degAddr = nullptr;
    if (!s2) {
        cudaFuncSetAttribute(gemm_tc_kernel<128, 0>,
                             cudaFuncAttributeMaxDynamicSharedMemorySize, smBytes);
        cudaFuncSetAttribute(gemm_tc_kernel<256, 1>,
                             cudaFuncAttributeMaxDynamicSharedMemorySize, smBytes);
        cudaStreamCreateWithFlags(&s2, cudaStreamNonBlocking);
        cudaEventCreateWithFlags(&evFork, cudaEventDisableTiming);
        cudaEventCreateWithFlags(&evJoin, cudaEventDisableTiming);
        cudaGetSymbolAddress(&degAddr, g_deg);
    }

    // fork: CSR build on s2, overlapped with in0+weights + gemm0
    cudaEventRecord(evFork, 0);
    cudaStreamWaitEvent(s2, evFork, 0);
    cudaMemsetAsync(degAddr, 0, n * sizeof(int), s2);
    deg_kernel<<<cdiv(halfE, T), T, 0, s2>>>(ei, E);
    scan1_kernel<<<nb, 512, 0, s2>>>(n);
    scan23_kernel<<<nb, 512, 0, s2>>>(nb, n);
    scatter_kernel<<<cdiv(halfE + n, T), T, 0, s2>>>(ei, E, halfE, n);
    cudaEventRecord(evJoin, s2);

    // main stream: feature pipeline (weight convert fused into build kernel)
    build_in0_kernel<<<buildBlocks + 256, T>>>(x, batch, clab, emb, W0, W1, W2, n, buildBlocks);

    dim3 gemm_grid(cdiv(n, 128), 2);
    const int WOFF[3] = {0, 256 * 128, 256 * 128 + 256 * 256};
    const float* asl[3] = {as0, as1, as2};
    const float* adl[3] = {ad0, ad1, ad2};
    const float* bl[3]  = {b0, b1, b2};
    float* y = (float*)d_out;

    for (int l = 0; l < 3; l++) {
        if (l == 0) gemm_tc_kernel<128, 0><<<gemm_grid, T, smBytes>>>(WOFF[0], n, asl[l], adl[l]);
        else        gemm_tc_kernel<256, 1><<<gemm_grid, T, smBytes>>>(WOFF[l], n, asl[l], adl[l]);

        if (l == 0) cudaStreamWaitEvent(0, evJoin, 0);   // join CSR before first agg

        if (l < 2) agg_kernel<false><<<aggBlocks, 128>>>(bl[l], nullptr, nullptr, nullptr, n);
        else       agg_kernel<true><<<aggBlocks, 128>>>(bl[l], clsW, clsb, y, n);
    }
}

// round 15
// speedup vs baseline: 1.0161x; 1.0161x over previous
#include <cuda_runtime.h>
#include <cuda_fp16.h>
#include <cstdint>

#define NN 50000
#define EEMAX 800000

// ---------------- scratch (static device globals; no allocation) -------------
__device__ __align__(16) __half g_in0[NN * 128];    // fp16 layer-0 input
__device__ __align__(16) __half g_feat[NN * 256];   // fp16 features
__device__ __align__(16) __half g_out[NN * 256];    // fp16 activated layer output
__device__ __align__(16) __half g_wtf[256 * 128 + 2 * 256 * 256];  // fp16 weights
__device__ float g_ssrc[NN * 4];
__device__ float g_sdst[NN * 4];
__device__ __align__(16) float g_ew[(EEMAX + NN) * 4];    // alpha cache (fp32: pre-exp)
__device__ __align__(16) __half g_ewh[(EEMAX + NN) * 4];  // exp-weight cache (fp16: ex in (0,1])
__device__ int   g_deg[NN];
__device__ int   g_cursor[NN];
__device__ int   g_rowptr[NN + 1];
__device__ int   g_csrc[EEMAX + NN];
__device__ int   g_bsum[512];

__device__ __forceinline__ float lrelu(float x, float s) { return x >= 0.f ? x : s * x; }

// fp16 mma with fp32 accumulate: same 10-bit mantissa as tf32-rna (R5/R8 lesson)
__device__ __forceinline__ void mma_f16(float4& c, const uint32_t a[4], const uint32_t b[2]) {
    asm volatile(
        "mma.sync.aligned.m16n8k16.row.col.f32.f16.f16.f32 "
        "{%0,%1,%2,%3}, {%4,%5,%6,%7}, {%8,%9}, {%0,%1,%2,%3};"
        : "+f"(c.x), "+f"(c.y), "+f"(c.z), "+f"(c.w)
        : "r"(a[0]), "r"(a[1]), "r"(a[2]), "r"(a[3]), "r"(b[0]), "r"(b[1]));
}

__device__ __forceinline__ void cp16(uint32_t smem_dst, const void* gsrc, int src_bytes) {
    asm volatile("cp.async.ca.shared.global [%0], [%1], 16, %2;\n"
                 :: "r"(smem_dst), "l"(gsrc), "r"(src_bytes));
}

__device__ __forceinline__ void edge_sd(const int* __restrict__ ei, int e, int E, int& s, int& d) {
    if (e < E) { s = ei[e]; d = ei[E + e]; }
    else       { s = e - E; d = e - E; }   // appended self-loops
}

// ---------------- layer-0 input build (fp16) + fused weight convert ----------
__global__ void build_in0_kernel(const float* __restrict__ x,
                                 const int* __restrict__ batch,
                                 const int* __restrict__ clab,
                                 const float* __restrict__ emb,
                                 const float* __restrict__ W0,
                                 const float* __restrict__ W1,
                                 const float* __restrict__ W2,
                                 int n, int nBuild) {
    if (blockIdx.x >= nBuild) {
        int i = (blockIdx.x - nBuild) * blockDim.x + threadIdx.x;
        const int S0 = 256 * 128, S1 = 256 * 256;
        if (i < S0)                 g_wtf[i] = __float2half_rn(W0[i]);
        if (i < S1) {
            g_wtf[S0 + i]      = __float2half_rn(W1[i]);
            g_wtf[S0 + S1 + i] = __float2half_rn(W2[i]);
        }
        return;
    }
    int gt = blockIdx.x * blockDim.x + threadIdx.x;
    int node = gt >> 5, lane = gt & 31;
    if (node >= n) return;
    float4 v;
    if (lane < 16) {
        v = reinterpret_cast<const float4*>(x + (size_t)node * 64)[lane];
    } else {
        int c = clab[batch[node]];
        v = reinterpret_cast<const float4*>(emb + (size_t)c * 64)[lane - 16];
    }
    __half2 h0 = __floats2half2_rn(v.x, v.y);
    __half2 h1 = __floats2half2_rn(v.z, v.w);
    *reinterpret_cast<uint2*>(g_in0 + (size_t)node * 128 + lane * 4) =
        make_uint2(*reinterpret_cast<uint32_t*>(&h0), *reinterpret_cast<uint32_t*>(&h1));
}

// ---------------- tensor-core GEMM + fused attention scores ------------------
#define SMSH (128 * 40)

template <int K, int SRC>
__global__ void __launch_bounds__(256, 2) gemm_tc_kernel(int woff, int M,
                                                         const float* __restrict__ asrc,
                                                         const float* __restrict__ adst) {
    constexpr int NT = K / 32;
    extern __shared__ __half smh[];
    const __half* __restrict__ A = (SRC == 0) ? g_in0 : g_out;
    const __half* __restrict__ Wm = g_wtf + woff;

    const int tid = threadIdx.x;
    const int warp = tid >> 5, lane = tid & 31;
    const int wm = warp >> 1;
    const int wn = warp & 1;
    const int g = lane >> 2, t4 = lane & 3;
    const int rowBase = blockIdx.x * 128;
    const int colBase = blockIdx.y * 128;

    const uint32_t sbase = (uint32_t)__cvta_generic_to_shared(smh);

    float4 c[2][8];
#pragma unroll
    for (int i = 0; i < 2; i++)
#pragma unroll
        for (int j = 0; j < 8; j++) c[i][j] = make_float4(0.f, 0.f, 0.f, 0.f);

    auto issue = [&](int t) {
        const int buf = t & 1;
        const int k0 = t * 32;
#pragma unroll
        for (int i = 0; i < 2; i++) {
            int f = tid + i * 256;
            int r = f >> 2, cc = (f & 3) * 8;
            int gr = rowBase + r;
            uint32_t da = sbase + (uint32_t)(buf * SMSH + r * 40 + cc) * 2u;
            cp16(da, A + (size_t)gr * K + k0 + cc, (gr < M) ? 16 : 0);
        }
#pragma unroll
        for (int i = 0; i < 2; i++) {
            int f = tid + i * 256;
            int r = f >> 2, cc = (f & 3) * 8;
            uint32_t db = sbase + (uint32_t)((2 + buf) * SMSH + r * 40 + cc) * 2u;
            cp16(db, Wm + (size_t)(colBase + r) * K + k0 + cc, 16);
        }
        asm volatile("cp.async.commit_group;\n" ::);
    };

    issue(0);

#pragma unroll 1
    for (int t = 0; t < NT; t++) {
        if (t + 1 < NT) {
            issue(t + 1);
            asm volatile("cp.async.wait_group 1;\n" ::);
        } else {
            asm volatile("cp.async.wait_group 0;\n" ::);
        }
        __syncthreads();
        const int buf = t & 1;
        const __half* Ab = smh + buf * SMSH;
        const __half* Bb = smh + (2 + buf) * SMSH;
#pragma unroll
        for (int ks = 0; ks < 2; ks++) {
            const int kb = ks * 16 + t4 * 2;
            uint32_t bfr[8][2];
#pragma unroll
            for (int j = 0; j < 8; j++) {
                int cn = wn * 64 + j * 8 + g;
                bfr[j][0] = *reinterpret_cast<const uint32_t*>(&Bb[cn * 40 + kb]);
                bfr[j][1] = *reinterpret_cast<const uint32_t*>(&Bb[cn * 40 + kb + 8]);
            }
            uint32_t afr[2][4];
#pragma unroll
            for (int i = 0; i < 2; i++) {
                int r = wm * 32 + i * 16 + g;
                afr[i][0] = *reinterpret_cast<const uint32_t*>(&Ab[r * 40 + kb]);
                afr[i][1] = *reinterpret_cast<const uint32_t*>(&Ab[(r + 8) * 40 + kb]);
                afr[i][2] = *reinterpret_cast<const uint32_t*>(&Ab[r * 40 + kb + 8]);
                afr[i][3] = *reinterpret_cast<const uint32_t*>(&Ab[(r + 8) * 40 + kb + 8]);
            }
#pragma unroll
            for (int i = 0; i < 2; i++)
#pragma unroll
                for (int j = 0; j < 8; j++) mma_f16(c[i][j], afr[i], bfr[j]);
        }
        __syncthreads();
    }

    // epilogue A: fp16 store to g_feat[M,256]
#pragma unroll
    for (int i = 0; i < 2; i++) {
#pragma unroll
        for (int j = 0; j < 8; j++) {
            int row0 = rowBase + wm * 32 + i * 16 + g;
            int coln = colBase + wn * 64 + j * 8 + 2 * t4;
            if (row0 < M)
                *reinterpret_cast<__half2*>(g_feat + (size_t)row0 * 256 + coln) =
                    __floats2half2_rn(c[i][j].x, c[i][j].y);
            if (row0 + 8 < M)
                *reinterpret_cast<__half2*>(g_feat + (size_t)(row0 + 8) * 256 + coln) =
                    __floats2half2_rn(c[i][j].z, c[i][j].w);
        }
    }

    // epilogue B: fused attention scores (warp's 64 cols == one head)
    {
        const int head = blockIdx.y * 2 + wn;
        const float* ah = asrc + head * 64;
        const float* dh = adst + head * 64;
        float ssp[4] = {0.f, 0.f, 0.f, 0.f}, sdp[4] = {0.f, 0.f, 0.f, 0.f};
#pragma unroll
        for (int j = 0; j < 8; j++) {
            int col = j * 8 + 2 * t4;
            float2 av = *reinterpret_cast<const float2*>(ah + col);
            float2 dv = *reinterpret_cast<const float2*>(dh + col);
#pragma unroll
            for (int i = 0; i < 2; i++) {
                ssp[i * 2]     += c[i][j].x * av.x + c[i][j].y * av.y;
                ssp[i * 2 + 1] += c[i][j].z * av.x + c[i][j].w * av.y;
                sdp[i * 2]     += c[i][j].x * dv.x + c[i][j].y * dv.y;
                sdp[i * 2 + 1] += c[i][j].z * dv.x + c[i][j].w * dv.y;
            }
        }
#pragma unroll
        for (int off = 1; off <= 2; off <<= 1) {
#pragma unroll
            for (int k = 0; k < 4; k++) {
                ssp[k] += __shfl_xor_sync(0xffffffffu, ssp[k], off);
                sdp[k] += __shfl_xor_sync(0xffffffffu, sdp[k], off);
            }
        }
        if (t4 == 0) {
#pragma unroll
            for (int k = 0; k < 4; k++) {
                int row = rowBase + wm * 32 + (k >> 1) * 16 + (k & 1) * 8 + g;
                if (row < M) {
                    g_ssrc[row * 4 + head] = ssp[k];
                    g_sdst[row * 4 + head] = sdp[k];
                }
            }
        }
    }
}

// ---------------- CSR build (R13 forms; scatter is ATOMG-latency bound) ------
__global__ void deg_kernel(const int* __restrict__ ei, int E, int ET) {
    int e = blockIdx.x * blockDim.x + threadIdx.x;
    if (e >= ET) return;
    int s, d; edge_sd(ei, e, E, s, d);
    atomicAdd(&g_deg[d], 1);
}

__global__ void scan1_kernel(int n) {
    __shared__ int sh[512];
    int i = blockIdx.x * 512 + threadIdx.x;
    int v = (i < n) ? g_deg[i] : 0;
    sh[threadIdx.x] = v;
    __syncthreads();
#pragma unroll
    for (int off = 1; off < 512; off <<= 1) {
        int t = (threadIdx.x >= off) ? sh[threadIdx.x - off] : 0;
        __syncthreads();
        if (threadIdx.x >= off) sh[threadIdx.x] += t;
        __syncthreads();
    }
    if (i < n) g_rowptr[i] = sh[threadIdx.x] - v;
    if (threadIdx.x == 511) g_bsum[blockIdx.x] = sh[511];
}

__global__ void scan23_kernel(int nb, int n) {
    __shared__ int sh[512];
    int v = (threadIdx.x < nb) ? g_bsum[threadIdx.x] : 0;
    sh[threadIdx.x] = v;
    __syncthreads();
#pragma unroll
    for (int off = 1; off < 512; off <<= 1) {
        int t = (threadIdx.x >= off) ? sh[threadIdx.x - off] : 0;
        __syncthreads();
        if (threadIdx.x >= off) sh[threadIdx.x] += t;
        __syncthreads();
    }
    int bpre = (blockIdx.x > 0) ? sh[blockIdx.x - 1] : 0;
    int i = blockIdx.x * 512 + threadIdx.x;
    if (i < n) {
        int r = g_rowptr[i] + bpre;
        g_rowptr[i] = r;
        g_cursor[i] = r;
    }
    if (blockIdx.x == 0 && threadIdx.x == 0) g_rowptr[n] = sh[nb - 1];
}

__global__ void scatter_kernel(const int* __restrict__ ei, int E, int ET) {
    int e = blockIdx.x * blockDim.x + threadIdx.x;
    if (e >= ET) return;
    int s, d; edge_sd(ei, e, E, s, d);
    int pos = atomicAdd(&g_cursor[d], 1);   // cursor pre-seeded with rowptr
    g_csrc[pos] = s;
}

// ---------------- fused softmax + aggregation (+ classifier on last layer) ---
// 2-edge unroll (4-edge regressed via register pressure: R11); ex cached fp16 (R15)
template <bool LAST>
__global__ void agg_kernel(const float* __restrict__ b,
                           const float* __restrict__ clsW,
                           const float* __restrict__ clsb,
                           float* __restrict__ y, int n) {
    int gt = blockIdx.x * blockDim.x + threadIdx.x;
    int dst = gt >> 5, lane = gt & 31;
    if (dst >= n) return;
    const int beg = g_rowptr[dst], end = g_rowptr[dst + 1];
    const float4 sd4 = *reinterpret_cast<const float4*>(g_sdst + (size_t)dst * 4);

    // phase 1: segment max per head; cache alpha (fp32) coalesced into g_ew
    const float NEG = __int_as_float(0xff800000);
    float4 mx = make_float4(NEG, NEG, NEG, NEG);
    for (int i = beg + lane; i < end; i += 32) {
        int s = g_csrc[i];
        float4 ss = *reinterpret_cast<const float4*>(g_ssrc + (size_t)s * 4);
        float4 a;
        a.x = lrelu(ss.x + sd4.x, 0.2f); a.y = lrelu(ss.y + sd4.y, 0.2f);
        a.z = lrelu(ss.z + sd4.z, 0.2f); a.w = lrelu(ss.w + sd4.w, 0.2f);
        reinterpret_cast<float4*>(g_ew)[i] = a;
        mx.x = fmaxf(mx.x, a.x); mx.y = fmaxf(mx.y, a.y);
        mx.z = fmaxf(mx.z, a.z); mx.w = fmaxf(mx.w, a.w);
    }
#pragma unroll
    for (int off = 16; off; off >>= 1) {
        mx.x = fmaxf(mx.x, __shfl_xor_sync(0xffffffffu, mx.x, off));
        mx.y = fmaxf(mx.y, __shfl_xor_sync(0xffffffffu, mx.y, off));
        mx.z = fmaxf(mx.z, __shfl_xor_sync(0xffffffffu, mx.z, off));
        mx.w = fmaxf(mx.w, __shfl_xor_sync(0xffffffffu, mx.w, off));
    }

    // phase 2: exp from cached alpha; store ex as fp16 (ex in (0,1]); sum fp32
    float4 den = make_float4(0.f, 0.f, 0.f, 0.f);
    for (int i = beg + lane; i < end; i += 32) {
        float4 a = reinterpret_cast<const float4*>(g_ew)[i];
        float4 ex;
        ex.x = __expf(a.x - mx.x); ex.y = __expf(a.y - mx.y);
        ex.z = __expf(a.z - mx.z); ex.w = __expf(a.w - mx.w);
        __half2 e0 = __floats2half2_rn(ex.x, ex.y);
        __half2 e1 = __floats2half2_rn(ex.z, ex.w);
        *reinterpret_cast<uint2*>(g_ewh + (size_t)i * 4) =
            make_uint2(*reinterpret_cast<uint32_t*>(&e0), *reinterpret_cast<uint32_t*>(&e1));
        den.x += ex.x; den.y += ex.y; den.z += ex.z; den.w += ex.w;
    }
#pragma unroll
    for (int off = 16; off; off >>= 1) {
        den.x += __shfl_xor_sync(0xffffffffu, den.x, off);
        den.y += __shfl_xor_sync(0xffffffffu, den.y, off);
        den.z += __shfl_xor_sync(0xffffffffu, den.z, off);
        den.w += __shfl_xor_sync(0xffffffffu, den.w, off);
    }

    const int h = lane >> 3;
    float dh = (h & 2) ? ((h & 1) ? den.w : den.z) : ((h & 1) ? den.y : den.x);
    const float invd = 1.f / (dh + 1e-16f);

    // phase 3: weighted aggregation over fp16 features, 2-edge unroll
    float2 acc[4];
#pragma unroll
    for (int j = 0; j < 4; j++) acc[j] = make_float2(0.f, 0.f);

    int i = beg;
    for (; i + 1 < end; i += 2) {
        int s0 = g_csrc[i], s1 = g_csrc[i + 1];
        float w0 = __half2float(g_ewh[(size_t)i * 4 + h]) * invd;
        float w1 = __half2float(g_ewh[(size_t)(i + 1) * 4 + h]) * invd;
        uint4 p0 = *reinterpret_cast<const uint4*>(g_feat + (size_t)s0 * 256 + lane * 8);
        uint4 p1 = *reinterpret_cast<const uint4*>(g_feat + (size_t)s1 * 256 + lane * 8);
        const __half2* q0 = reinterpret_cast<const __half2*>(&p0);
        const __half2* q1 = reinterpret_cast<const __half2*>(&p1);
#pragma unroll
        for (int j = 0; j < 4; j++) {
            float2 f0 = __half22float2(q0[j]);
            float2 f1 = __half22float2(q1[j]);
            acc[j].x += w0 * f0.x + w1 * f1.x;
            acc[j].y += w0 * f0.y + w1 * f1.y;
        }
    }
    if (i < end) {
        int s0 = g_csrc[i];
        float w0 = __half2float(g_ewh[(size_t)i * 4 + h]) * invd;
        uint4 p0 = *reinterpret_cast<const uint4*>(g_feat + (size_t)s0 * 256 + lane * 8);
        const __half2* q0 = reinterpret_cast<const __half2*>(&p0);
#pragma unroll
        for (int j = 0; j < 4; j++) {
            float2 f0 = __half22float2(q0[j]);
            acc[j].x += w0 * f0.x;
            acc[j].y += w0 * f0.y;
        }
    }

    const float4 b0 = reinterpret_cast<const float4*>(b)[lane * 2];
    const float4 b1 = reinterpret_cast<const float4*>(b)[lane * 2 + 1];
    float o[8];
    o[0] = lrelu(acc[0].x + b0.x, 0.01f); o[1] = lrelu(acc[0].y + b0.y, 0.01f);
    o[2] = lrelu(acc[1].x + b0.z, 0.01f); o[3] = lrelu(acc[1].y + b0.w, 0.01f);
    o[4] = lrelu(acc[2].x + b1.x, 0.01f); o[5] = lrelu(acc[2].y + b1.y, 0.01f);
    o[6] = lrelu(acc[3].x + b1.z, 0.01f); o[7] = lrelu(acc[3].y + b1.w, 0.01f);

    if (!LAST) {
        __half2 h0 = __floats2half2_rn(o[0], o[1]);
        __half2 h1 = __floats2half2_rn(o[2], o[3]);
        __half2 h2 = __floats2half2_rn(o[4], o[5]);
        __half2 h3 = __floats2half2_rn(o[6], o[7]);
        *reinterpret_cast<uint4*>(g_out + (size_t)dst * 256 + lane * 8) =
            make_uint4(*reinterpret_cast<uint32_t*>(&h0), *reinterpret_cast<uint32_t*>(&h1),
                       *reinterpret_cast<uint32_t*>(&h2), *reinterpret_cast<uint32_t*>(&h3));
    } else {
        const float4 w0 = reinterpret_cast<const float4*>(clsW)[lane * 2];
        const float4 w1 = reinterpret_cast<const float4*>(clsW)[lane * 2 + 1];
        float sum = o[0] * w0.x + o[1] * w0.y + o[2] * w0.z + o[3] * w0.w +
                    o[4] * w1.x + o[5] * w1.y + o[6] * w1.z + o[7] * w1.w;
#pragma unroll
        for (int off = 16; off; off >>= 1) sum += __shfl_xor_sync(0xffffffffu, sum, off);
        if (lane == 0) y[dst] = sum + clsb[0];
    }
}

static inline int cdiv(int a, int b) { return (a + b - 1) / b; }

extern "C" void kernel_launch(void* const* d_in, const int* in_sizes, int n_in,
                              void* d_out, int out_size) {
    const float* x     = (const float*)d_in[0];
    const int*   ei    = (const int*)d_in[1];
    const int*   batch = (const int*)d_in[2];
    const int*   clab  = (const int*)d_in[3];
    const float* emb   = (const float*)d_in[4];
    const float* W0    = (const float*)d_in[5];
    const float* as0   = (const float*)d_in[6];
    const float* ad0   = (const float*)d_in[7];
    const float* b0    = (const float*)d_in[8];
    const float* W1    = (const float*)d_in[9];
    const float* as1   = (const float*)d_in[10];
    const float* ad1   = (const float*)d_in[11];
    const float* b1    = (const float*)d_in[12];
    const float* W2    = (const float*)d_in[13];
    const float* as2   = (const float*)d_in[14];
    const float* ad2   = (const float*)d_in[15];
    const float* b2    = (const float*)d_in[16];
    const float* clsW  = (const float*)d_in[17];
    const float* clsb  = (const float*)d_in[18];

    int n  = in_sizes[0] / 64;   // 50000
    int E  = in_sizes[1] / 2;    // 800000
    int ET = E + n;

    const int T = 256;
    int buildBlocks = cdiv(n * 32, T);
    int aggBlocks = cdiv(n * 32, 128);
    int nb = cdiv(n, 512);
    const int smBytes = 4 * SMSH * sizeof(__half);   // 40960 (2-stage)

    static cudaStream_t s2 = nullptr;
    static cudaEvent_t evFork = nullptr, evJoin = nullptr;
    static void* degAddr = nullptr;
    if (!s2) {
        cudaFuncSetAttribute(gemm_tc_kernel<128, 0>,
                             cudaFuncAttributeMaxDynamicSharedMemorySize, smBytes);
        cudaFuncSetAttribute(gemm_tc_kernel<256, 1>,
                             cudaFuncAttributeMaxDynamicSharedMemorySize, smBytes);
        cudaStreamCreateWithFlags(&s2, cudaStreamNonBlocking);
        cudaEventCreateWithFlags(&evFork, cudaEventDisableTiming);
        cudaEventCreateWithFlags(&evJoin, cudaEventDisableTiming);
        cudaGetSymbolAddress(&degAddr, g_deg);
    }

    // fork: CSR build on s2, overlapped with in0+weights + gemm0
    cudaEventRecord(evFork, 0);
    cudaStreamWaitEvent(s2, evFork, 0);
    cudaMemsetAsync(degAddr, 0, n * sizeof(int), s2);
    deg_kernel<<<cdiv(ET, T), T, 0, s2>>>(ei, E, ET);
    scan1_kernel<<<nb, 512, 0, s2>>>(n);
    scan23_kernel<<<nb, 512, 0, s2>>>(nb, n);
    scatter_kernel<<<cdiv(ET, T), T, 0, s2>>>(ei, E, ET);
    cudaEventRecord(evJoin, s2);

    // main stream: feature pipeline (weight convert fused into build kernel)
    build_in0_kernel<<<buildBlocks + 256, T>>>(x, batch, clab, emb, W0, W1, W2, n, buildBlocks);

    dim3 gemm_grid(cdiv(n, 128), 2);
    const int WOFF[3] = {0, 256 * 128, 256 * 128 + 256 * 256};
    const float* asl[3] = {as0, as1, as2};
    const float* adl[3] = {ad0, ad1, ad2};
    const float* bl[3]  = {b0, b1, b2};
    float* y = (float*)d_out;

    for (int l = 0; l < 3; l++) {
        if (l == 0) gemm_tc_kernel<128, 0><<<gemm_grid, T, smBytes>>>(WOFF[0], n, asl[l], adl[l]);
        else        gemm_tc_kernel<256, 1><<<gemm_grid, T, smBytes>>>(WOFF[l], n, asl[l], adl[l]);

        if (l == 0) cudaStreamWaitEvent(0, evJoin, 0);   // join CSR before first agg

        if (l < 2) agg_kernel<false><<<aggBlocks, 128>>>(bl[l], nullptr, nullptr, nullptr, n);
        else       agg_kernel<true><<<aggBlocks, 128>>>(bl[l], clsW, clsb, y, n);
    }
}

// round 16
// speedup vs baseline: 1.0257x; 1.0094x over previous
#include <cuda_runtime.h>
#include <cuda_fp16.h>
#include <cstdint>

#define NN 50000
#define EEMAX 800000

// ---------------- scratch (static device globals; no allocation) -------------
__device__ __align__(16) __half g_in0[NN * 128];    // fp16 layer-0 input
__device__ __align__(16) __half g_feat[NN * 256];   // fp16 features
__device__ __align__(16) __half g_out[NN * 256];    // fp16 activated layer output
__device__ __align__(16) __half g_wtf[256 * 128 + 2 * 256 * 256];  // fp16 weights
__device__ float g_ssrc[NN * 4];
__device__ float g_sdst[NN * 4];
__device__ __align__(16) float g_ew[(EEMAX + NN) * 4];    // alpha cache (fp32: pre-exp)
__device__ __align__(16) __half g_ewh[(EEMAX + NN) * 4];  // exp-weight cache (fp16: ex in (0,1])
__device__ int   g_deg[NN];
__device__ int   g_epos[EEMAX + NN];   // per-edge slot within its dst row (from deg pass)
__device__ int   g_rowptr[NN + 1];
__device__ int   g_csrc[EEMAX + NN];
__device__ int   g_bsum[512];

__device__ __forceinline__ float lrelu(float x, float s) { return x >= 0.f ? x : s * x; }

// fp16 mma with fp32 accumulate: same 10-bit mantissa as tf32-rna (R5/R8 lesson)
__device__ __forceinline__ void mma_f16(float4& c, const uint32_t a[4], const uint32_t b[2]) {
    asm volatile(
        "mma.sync.aligned.m16n8k16.row.col.f32.f16.f16.f32 "
        "{%0,%1,%2,%3}, {%4,%5,%6,%7}, {%8,%9}, {%0,%1,%2,%3};"
        : "+f"(c.x), "+f"(c.y), "+f"(c.z), "+f"(c.w)
        : "r"(a[0]), "r"(a[1]), "r"(a[2]), "r"(a[3]), "r"(b[0]), "r"(b[1]));
}

__device__ __forceinline__ void cp16(uint32_t smem_dst, const void* gsrc, int src_bytes) {
    asm volatile("cp.async.ca.shared.global [%0], [%1], 16, %2;\n"
                 :: "r"(smem_dst), "l"(gsrc), "r"(src_bytes));
}

__device__ __forceinline__ void edge_sd(const int* __restrict__ ei, int e, int E, int& s, int& d) {
    if (e < E) { s = ei[e]; d = ei[E + e]; }
    else       { s = e - E; d = e - E; }   // appended self-loops
}

// ---------------- layer-0 input build (fp16) + fused weight convert ----------
__global__ void build_in0_kernel(const float* __restrict__ x,
                                 const int* __restrict__ batch,
                                 const int* __restrict__ clab,
                                 const float* __restrict__ emb,
                                 const float* __restrict__ W0,
                                 const float* __restrict__ W1,
                                 const float* __restrict__ W2,
                                 int n, int nBuild) {
    if (blockIdx.x >= nBuild) {
        int i = (blockIdx.x - nBuild) * blockDim.x + threadIdx.x;
        const int S0 = 256 * 128, S1 = 256 * 256;
        if (i < S0)                 g_wtf[i] = __float2half_rn(W0[i]);
        if (i < S1) {
            g_wtf[S0 + i]      = __float2half_rn(W1[i]);
            g_wtf[S0 + S1 + i] = __float2half_rn(W2[i]);
        }
        return;
    }
    int gt = blockIdx.x * blockDim.x + threadIdx.x;
    int node = gt >> 5, lane = gt & 31;
    if (node >= n) return;
    float4 v;
    if (lane < 16) {
        v = reinterpret_cast<const float4*>(x + (size_t)node * 64)[lane];
    } else {
        int c = clab[batch[node]];
        v = reinterpret_cast<const float4*>(emb + (size_t)c * 64)[lane - 16];
    }
    __half2 h0 = __floats2half2_rn(v.x, v.y);
    __half2 h1 = __floats2half2_rn(v.z, v.w);
    *reinterpret_cast<uint2*>(g_in0 + (size_t)node * 128 + lane * 4) =
        make_uint2(*reinterpret_cast<uint32_t*>(&h0), *reinterpret_cast<uint32_t*>(&h1));
}

// ---------------- tensor-core GEMM + fused attention scores ------------------
#define SMSH (128 * 40)

template <int K, int SRC>
__global__ void __launch_bounds__(256, 2) gemm_tc_kernel(int woff, int M,
                                                         const float* __restrict__ asrc,
                                                         const float* __restrict__ adst) {
    constexpr int NT = K / 32;
    extern __shared__ __half smh[];
    const __half* __restrict__ A = (SRC == 0) ? g_in0 : g_out;
    const __half* __restrict__ Wm = g_wtf + woff;

    const int tid = threadIdx.x;
    const int warp = tid >> 5, lane = tid & 31;
    const int wm = warp >> 1;
    const int wn = warp & 1;
    const int g = lane >> 2, t4 = lane & 3;
    const int rowBase = blockIdx.x * 128;
    const int colBase = blockIdx.y * 128;

    const uint32_t sbase = (uint32_t)__cvta_generic_to_shared(smh);

    float4 c[2][8];
#pragma unroll
    for (int i = 0; i < 2; i++)
#pragma unroll
        for (int j = 0; j < 8; j++) c[i][j] = make_float4(0.f, 0.f, 0.f, 0.f);

    auto issue = [&](int t) {
        const int buf = t & 1;
        const int k0 = t * 32;
#pragma unroll
        for (int i = 0; i < 2; i++) {
            int f = tid + i * 256;
            int r = f >> 2, cc = (f & 3) * 8;
            int gr = rowBase + r;
            uint32_t da = sbase + (uint32_t)(buf * SMSH + r * 40 + cc) * 2u;
            cp16(da, A + (size_t)gr * K + k0 + cc, (gr < M) ? 16 : 0);
        }
#pragma unroll
        for (int i = 0; i < 2; i++) {
            int f = tid + i * 256;
            int r = f >> 2, cc = (f & 3) * 8;
            uint32_t db = sbase + (uint32_t)((2 + buf) * SMSH + r * 40 + cc) * 2u;
            cp16(db, Wm + (size_t)(colBase + r) * K + k0 + cc, 16);
        }
        asm volatile("cp.async.commit_group;\n" ::);
    };

    issue(0);

#pragma unroll 1
    for (int t = 0; t < NT; t++) {
        if (t + 1 < NT) {
            issue(t + 1);
            asm volatile("cp.async.wait_group 1;\n" ::);
        } else {
            asm volatile("cp.async.wait_group 0;\n" ::);
        }
        __syncthreads();
        const int buf = t & 1;
        const __half* Ab = smh + buf * SMSH;
        const __half* Bb = smh + (2 + buf) * SMSH;
#pragma unroll
        for (int ks = 0; ks < 2; ks++) {
            const int kb = ks * 16 + t4 * 2;
            uint32_t bfr[8][2];
#pragma unroll
            for (int j = 0; j < 8; j++) {
                int cn = wn * 64 + j * 8 + g;
                bfr[j][0] = *reinterpret_cast<const uint32_t*>(&Bb[cn * 40 + kb]);
                bfr[j][1] = *reinterpret_cast<const uint32_t*>(&Bb[cn * 40 + kb + 8]);
            }
            uint32_t afr[2][4];
#pragma unroll
            for (int i = 0; i < 2; i++) {
                int r = wm * 32 + i * 16 + g;
                afr[i][0] = *reinterpret_cast<const uint32_t*>(&Ab[r * 40 + kb]);
                afr[i][1] = *reinterpret_cast<const uint32_t*>(&Ab[(r + 8) * 40 + kb]);
                afr[i][2] = *reinterpret_cast<const uint32_t*>(&Ab[r * 40 + kb + 8]);
                afr[i][3] = *reinterpret_cast<const uint32_t*>(&Ab[(r + 8) * 40 + kb + 8]);
            }
#pragma unroll
            for (int i = 0; i < 2; i++)
#pragma unroll
                for (int j = 0; j < 8; j++) mma_f16(c[i][j], afr[i], bfr[j]);
        }
        __syncthreads();
    }

    // epilogue A: fp16 store to g_feat[M,256]
#pragma unroll
    for (int i = 0; i < 2; i++) {
#pragma unroll
        for (int j = 0; j < 8; j++) {
            int row0 = rowBase + wm * 32 + i * 16 + g;
            int coln = colBase + wn * 64 + j * 8 + 2 * t4;
            if (row0 < M)
                *reinterpret_cast<__half2*>(g_feat + (size_t)row0 * 256 + coln) =
                    __floats2half2_rn(c[i][j].x, c[i][j].y);
            if (row0 + 8 < M)
                *reinterpret_cast<__half2*>(g_feat + (size_t)(row0 + 8) * 256 + coln) =
                    __floats2half2_rn(c[i][j].z, c[i][j].w);
        }
    }

    // epilogue B: fused attention scores (warp's 64 cols == one head)
    {
        const int head = blockIdx.y * 2 + wn;
        const float* ah = asrc + head * 64;
        const float* dh = adst + head * 64;
        float ssp[4] = {0.f, 0.f, 0.f, 0.f}, sdp[4] = {0.f, 0.f, 0.f, 0.f};
#pragma unroll
        for (int j = 0; j < 8; j++) {
            int col = j * 8 + 2 * t4;
            float2 av = *reinterpret_cast<const float2*>(ah + col);
            float2 dv = *reinterpret_cast<const float2*>(dh + col);
#pragma unroll
            for (int i = 0; i < 2; i++) {
                ssp[i * 2]     += c[i][j].x * av.x + c[i][j].y * av.y;
                ssp[i * 2 + 1] += c[i][j].z * av.x + c[i][j].w * av.y;
                sdp[i * 2]     += c[i][j].x * dv.x + c[i][j].y * dv.y;
                sdp[i * 2 + 1] += c[i][j].z * dv.x + c[i][j].w * dv.y;
            }
        }
#pragma unroll
        for (int off = 1; off <= 2; off <<= 1) {
#pragma unroll
            for (int k = 0; k < 4; k++) {
                ssp[k] += __shfl_xor_sync(0xffffffffu, ssp[k], off);
                sdp[k] += __shfl_xor_sync(0xffffffffu, sdp[k], off);
            }
        }
        if (t4 == 0) {
#pragma unroll
            for (int k = 0; k < 4; k++) {
                int row = rowBase + wm * 32 + (k >> 1) * 16 + (k & 1) * 8 + g;
                if (row < M) {
                    g_ssrc[row * 4 + head] = ssp[k];
                    g_sdst[row * 4 + head] = sdp[k];
                }
            }
        }
    }
}

// ---------------- CSR build --------------------------------------------------
// deg: the atomic's return value IS the edge's slot within its dst row (R16):
// scatter then needs no atomic at all.
__global__ void deg_kernel(const int* __restrict__ ei, int E, int ET) {
    int e = blockIdx.x * blockDim.x + threadIdx.x;
    if (e >= ET) return;
    int s, d; edge_sd(ei, e, E, s, d);
    g_epos[e] = atomicAdd(&g_deg[d], 1);
}

__global__ void scan1_kernel(int n) {
    __shared__ int sh[512];
    int i = blockIdx.x * 512 + threadIdx.x;
    int v = (i < n) ? g_deg[i] : 0;
    sh[threadIdx.x] = v;
    __syncthreads();
#pragma unroll
    for (int off = 1; off < 512; off <<= 1) {
        int t = (threadIdx.x >= off) ? sh[threadIdx.x - off] : 0;
        __syncthreads();
        if (threadIdx.x >= off) sh[threadIdx.x] += t;
        __syncthreads();
    }
    if (i < n) g_rowptr[i] = sh[threadIdx.x] - v;
    if (threadIdx.x == 511) g_bsum[blockIdx.x] = sh[511];
}

__global__ void scan23_kernel(int nb, int n) {
    __shared__ int sh[512];
    int v = (threadIdx.x < nb) ? g_bsum[threadIdx.x] : 0;
    sh[threadIdx.x] = v;
    __syncthreads();
#pragma unroll
    for (int off = 1; off < 512; off <<= 1) {
        int t = (threadIdx.x >= off) ? sh[threadIdx.x - off] : 0;
        __syncthreads();
        if (threadIdx.x >= off) sh[threadIdx.x] += t;
        __syncthreads();
    }
    int bpre = (blockIdx.x > 0) ? sh[blockIdx.x - 1] : 0;
    int i = blockIdx.x * 512 + threadIdx.x;
    if (i < n) g_rowptr[i] += bpre;
    if (blockIdx.x == 0 && threadIdx.x == 0) g_rowptr[n] = sh[nb - 1];
}

// scatter: atomic-free — slot was captured in the deg pass
__global__ void scatter_kernel(const int* __restrict__ ei, int E, int ET) {
    int e = blockIdx.x * blockDim.x + threadIdx.x;
    if (e >= ET) return;
    int s, d; edge_sd(ei, e, E, s, d);
    g_csrc[g_rowptr[d] + g_epos[e]] = s;
}

// ---------------- fused softmax + aggregation (+ classifier on last layer) ---
// 2-edge unroll (4-edge regressed via register pressure: R11); ex cached fp16 (R15)
template <bool LAST>
__global__ void agg_kernel(const float* __restrict__ b,
                           const float* __restrict__ clsW,
                           const float* __restrict__ clsb,
                           float* __restrict__ y, int n) {
    int gt = blockIdx.x * blockDim.x + threadIdx.x;
    int dst = gt >> 5, lane = gt & 31;
    if (dst >= n) return;
    const int beg = g_rowptr[dst], end = g_rowptr[dst + 1];
    const float4 sd4 = *reinterpret_cast<const float4*>(g_sdst + (size_t)dst * 4);

    // phase 1: segment max per head; cache alpha (fp32) coalesced into g_ew
    const float NEG = __int_as_float(0xff800000);
    float4 mx = make_float4(NEG, NEG, NEG, NEG);
    for (int i = beg + lane; i < end; i += 32) {
        int s = g_csrc[i];
        float4 ss = *reinterpret_cast<const float4*>(g_ssrc + (size_t)s * 4);
        float4 a;
        a.x = lrelu(ss.x + sd4.x, 0.2f); a.y = lrelu(ss.y + sd4.y, 0.2f);
        a.z = lrelu(ss.z + sd4.z, 0.2f); a.w = lrelu(ss.w + sd4.w, 0.2f);
        reinterpret_cast<float4*>(g_ew)[i] = a;
        mx.x = fmaxf(mx.x, a.x); mx.y = fmaxf(mx.y, a.y);
        mx.z = fmaxf(mx.z, a.z); mx.w = fmaxf(mx.w, a.w);
    }
#pragma unroll
    for (int off = 16; off; off >>= 1) {
        mx.x = fmaxf(mx.x, __shfl_xor_sync(0xffffffffu, mx.x, off));
        mx.y = fmaxf(mx.y, __shfl_xor_sync(0xffffffffu, mx.y, off));
        mx.z = fmaxf(mx.z, __shfl_xor_sync(0xffffffffu, mx.z, off));
        mx.w = fmaxf(mx.w, __shfl_xor_sync(0xffffffffu, mx.w, off));
    }

    // phase 2: exp from cached alpha; store ex as fp16 (ex in (0,1]); sum fp32
    float4 den = make_float4(0.f, 0.f, 0.f, 0.f);
    for (int i = beg + lane; i < end; i += 32) {
        float4 a = reinterpret_cast<const float4*>(g_ew)[i];
        float4 ex;
        ex.x = __expf(a.x - mx.x); ex.y = __expf(a.y - mx.y);
        ex.z = __expf(a.z - mx.z); ex.w = __expf(a.w - mx.w);
        __half2 e0 = __floats2half2_rn(ex.x, ex.y);
        __half2 e1 = __floats2half2_rn(ex.z, ex.w);
        *reinterpret_cast<uint2*>(g_ewh + (size_t)i * 4) =
            make_uint2(*reinterpret_cast<uint32_t*>(&e0), *reinterpret_cast<uint32_t*>(&e1));
        den.x += ex.x; den.y += ex.y; den.z += ex.z; den.w += ex.w;
    }
#pragma unroll
    for (int off = 16; off; off >>= 1) {
        den.x += __shfl_xor_sync(0xffffffffu, den.x, off);
        den.y += __shfl_xor_sync(0xffffffffu, den.y, off);
        den.z += __shfl_xor_sync(0xffffffffu, den.z, off);
        den.w += __shfl_xor_sync(0xffffffffu, den.w, off);
    }

    const int h = lane >> 3;
    float dh = (h & 2) ? ((h & 1) ? den.w : den.z) : ((h & 1) ? den.y : den.x);
    const float invd = 1.f / (dh + 1e-16f);

    // phase 3: weighted aggregation over fp16 features, 2-edge unroll
    float2 acc[4];
#pragma unroll
    for (int j = 0; j < 4; j++) acc[j] = make_float2(0.f, 0.f);

    int i = beg;
    for (; i + 1 < end; i += 2) {
        int s0 = g_csrc[i], s1 = g_csrc[i + 1];
        float w0 = __half2float(g_ewh[(size_t)i * 4 + h]) * invd;
        float w1 = __half2float(g_ewh[(size_t)(i + 1) * 4 + h]) * invd;
        uint4 p0 = *reinterpret_cast<const uint4*>(g_feat + (size_t)s0 * 256 + lane * 8);
        uint4 p1 = *reinterpret_cast<const uint4*>(g_feat + (size_t)s1 * 256 + lane * 8);
        const __half2* q0 = reinterpret_cast<const __half2*>(&p0);
        const __half2* q1 = reinterpret_cast<const __half2*>(&p1);
#pragma unroll
        for (int j = 0; j < 4; j++) {
            float2 f0 = __half22float2(q0[j]);
            float2 f1 = __half22float2(q1[j]);
            acc[j].x += w0 * f0.x + w1 * f1.x;
            acc[j].y += w0 * f0.y + w1 * f1.y;
        }
    }
    if (i < end) {
        int s0 = g_csrc[i];
        float w0 = __half2float(g_ewh[(size_t)i * 4 + h]) * invd;
        uint4 p0 = *reinterpret_cast<const uint4*>(g_feat + (size_t)s0 * 256 + lane * 8);
        const __half2* q0 = reinterpret_cast<const __half2*>(&p0);
#pragma unroll
        for (int j = 0; j < 4; j++) {
            float2 f0 = __half22float2(q0[j]);
            acc[j].x += w0 * f0.x;
            acc[j].y += w0 * f0.y;
        }
    }

    const float4 b0 = reinterpret_cast<const float4*>(b)[lane * 2];
    const float4 b1 = reinterpret_cast<const float4*>(b)[lane * 2 + 1];
    float o[8];
    o[0] = lrelu(acc[0].x + b0.x, 0.01f); o[1] = lrelu(acc[0].y + b0.y, 0.01f);
    o[2] = lrelu(acc[1].x + b0.z, 0.01f); o[3] = lrelu(acc[1].y + b0.w, 0.01f);
    o[4] = lrelu(acc[2].x + b1.x, 0.01f); o[5] = lrelu(acc[2].y + b1.y, 0.01f);
    o[6] = lrelu(acc[3].x + b1.z, 0.01f); o[7] = lrelu(acc[3].y + b1.w, 0.01f);

    if (!LAST) {
        __half2 h0 = __floats2half2_rn(o[0], o[1]);
        __half2 h1 = __floats2half2_rn(o[2], o[3]);
        __half2 h2 = __floats2half2_rn(o[4], o[5]);
        __half2 h3 = __floats2half2_rn(o[6], o[7]);
        *reinterpret_cast<uint4*>(g_out + (size_t)dst * 256 + lane * 8) =
            make_uint4(*reinterpret_cast<uint32_t*>(&h0), *reinterpret_cast<uint32_t*>(&h1),
                       *reinterpret_cast<uint32_t*>(&h2), *reinterpret_cast<uint32_t*>(&h3));
    } else {
        const float4 w0 = reinterpret_cast<const float4*>(clsW)[lane * 2];
        const float4 w1 = reinterpret_cast<const float4*>(clsW)[lane * 2 + 1];
        float sum = o[0] * w0.x + o[1] * w0.y + o[2] * w0.z + o[3] * w0.w +
                    o[4] * w1.x + o[5] * w1.y + o[6] * w1.z + o[7] * w1.w;
#pragma unroll
        for (int off = 16; off; off >>= 1) sum += __shfl_xor_sync(0xffffffffu, sum, off);
        if (lane == 0) y[dst] = sum + clsb[0];
    }
}

static inline int cdiv(int a, int b) { return (a + b - 1) / b; }

extern "C" void kernel_launch(void* const* d_in, const int* in_sizes, int n_in,
                              void* d_out, int out_size) {
    const float* x     = (const float*)d_in[0];
    const int*   ei    = (const int*)d_in[1];
    const int*   batch = (const int*)d_in[2];
    const int*   clab  = (const int*)d_in[3];
    const float* emb   = (const float*)d_in[4];
    const float* W0    = (const float*)d_in[5];
    const float* as0   = (const float*)d_in[6];
    const float* ad0   = (const float*)d_in[7];
    const float* b0    = (const float*)d_in[8];
    const float* W1    = (const float*)d_in[9];
    const float* as1   = (const float*)d_in[10];
    const float* ad1   = (const float*)d_in[11];
    const float* b1    = (const float*)d_in[12];
    const float* W2    = (const float*)d_in[13];
    const float* as2   = (const float*)d_in[14];
    const float* ad2   = (const float*)d_in[15];
    const float* b2    = (const float*)d_in[16];
    const float* clsW  = (const float*)d_in[17];
    const float* clsb  = (const float*)d_in[18];

    int n  = in_sizes[0] / 64;   // 50000
    int E  = in_sizes[1] / 2;    // 800000
    int ET = E + n;

    const int T = 256;
    int buildBlocks = cdiv(n * 32, T);
    int aggBlocks = cdiv(n * 32, 128);
    int nb = cdiv(n, 512);
    const int smBytes = 4 * SMSH * sizeof(__half);   // 40960 (2-stage)

    static cudaStream_t s2 = nullptr;
    static cudaEvent_t evFork = nullptr, evJoin = nullptr;
    static void* degAddr = nullptr;
    if (!s2) {
        cudaFuncSetAttribute(gemm_tc_kernel<128, 0>,
                             cudaFuncAttributeMaxDynamicSharedMemorySize, smBytes);
        cudaFuncSetAttribute(gemm_tc_kernel<256, 1>,
                             cudaFuncAttributeMaxDynamicSharedMemorySize, smBytes);
        cudaStreamCreateWithFlags(&s2, cudaStreamNonBlocking);
        cudaEventCreateWithFlags(&evFork, cudaEventDisableTiming);
        cudaEventCreateWithFlags(&evJoin, cudaEventDisableTiming);
        cudaGetSymbolAddress(&degAddr, g_deg);
    }

    // fork: CSR build on s2, overlapped with in0+weights + gemm0
    cudaEventRecord(evFork, 0);
    cudaStreamWaitEvent(s2, evFork, 0);
    cudaMemsetAsync(degAddr, 0, n * sizeof(int), s2);
    deg_kernel<<<cdiv(ET, T), T, 0, s2>>>(ei, E, ET);
    scan1_kernel<<<nb, 512, 0, s2>>>(n);
    scan23_kernel<<<nb, 512, 0, s2>>>(nb, n);
    scatter_kernel<<<cdiv(ET, T), T, 0, s2>>>(ei, E, ET);
    cudaEventRecord(evJoin, s2);

    // main stream: feature pipeline (weight convert fused into build kernel)
    build_in0_kernel<<<buildBlocks + 256, T>>>(x, batch, clab, emb, W0, W1, W2, n, buildBlocks);

    dim3 gemm_grid(cdiv(n, 128), 2);
    const int WOFF[3] = {0, 256 * 128, 256 * 128 + 256 * 256};
    const float* asl[3] = {as0, as1, as2};
    const float* adl[3] = {ad0, ad1, ad2};
    const float* bl[3]  = {b0, b1, b2};
    float* y = (float*)d_out;

    for (int l = 0; l < 3; l++) {
        if (l == 0) gemm_tc_kernel<128, 0><<<gemm_grid, T, smBytes>>>(WOFF[0], n, asl[l], adl[l]);
        else        gemm_tc_kernel<256, 1><<<gemm_grid, T, smBytes>>>(WOFF[l], n, asl[l], adl[l]);

        if (l == 0) cudaStreamWaitEvent(0, evJoin, 0);   // join CSR before first agg

        if (l < 2) agg_kernel<false><<<aggBlocks, 128>>>(bl[l], nullptr, nullptr, nullptr, n);
        else       agg_kernel<true><<<aggBlocks, 128>>>(bl[l], clsW, clsb, y, n);
    }
}

// round 17
// speedup vs baseline: 1.0336x; 1.0077x over previous
#include <cuda_runtime.h>
#include <cuda_fp16.h>
#include <cstdint>

#define NN 50000
#define EEMAX 800000

// ---------------- scratch (static device globals; no allocation) -------------
__device__ __align__(16) __half g_in0[NN * 128];    // fp16 layer-0 input
__device__ __align__(16) __half g_feat[NN * 256];   // fp16 features
__device__ __align__(16) __half g_out[NN * 256];    // fp16 activated layer output
__device__ __align__(16) __half g_wtf[256 * 128 + 2 * 256 * 256];  // fp16 weights
__device__ float g_ssrc[NN * 4];
__device__ float g_sdst[NN * 4];
__device__ int   g_deg[NN];
__device__ int   g_epos[EEMAX + NN];   // per-edge slot within its dst row (from deg pass)
__device__ int   g_rowptr[NN + 1];
__device__ int   g_csrc[EEMAX + NN];
__device__ int   g_bsum[512];

__device__ __forceinline__ float lrelu(float x, float s) { return x >= 0.f ? x : s * x; }

// fp16 mma with fp32 accumulate: same 10-bit mantissa as tf32-rna (R5/R8 lesson)
__device__ __forceinline__ void mma_f16(float4& c, const uint32_t a[4], const uint32_t b[2]) {
    asm volatile(
        "mma.sync.aligned.m16n8k16.row.col.f32.f16.f16.f32 "
        "{%0,%1,%2,%3}, {%4,%5,%6,%7}, {%8,%9}, {%0,%1,%2,%3};"
        : "+f"(c.x), "+f"(c.y), "+f"(c.z), "+f"(c.w)
        : "r"(a[0]), "r"(a[1]), "r"(a[2]), "r"(a[3]), "r"(b[0]), "r"(b[1]));
}

__device__ __forceinline__ void cp16(uint32_t smem_dst, const void* gsrc, int src_bytes) {
    asm volatile("cp.async.ca.shared.global [%0], [%1], 16, %2;\n"
                 :: "r"(smem_dst), "l"(gsrc), "r"(src_bytes));
}

__device__ __forceinline__ void edge_sd(const int* __restrict__ ei, int e, int E, int& s, int& d) {
    if (e < E) { s = ei[e]; d = ei[E + e]; }
    else       { s = e - E; d = e - E; }   // appended self-loops
}

// ---------------- layer-0 input build (fp16) + fused weight convert ----------
__global__ void build_in0_kernel(const float* __restrict__ x,
                                 const int* __restrict__ batch,
                                 const int* __restrict__ clab,
                                 const float* __restrict__ emb,
                                 const float* __restrict__ W0,
                                 const float* __restrict__ W1,
                                 const float* __restrict__ W2,
                                 int n, int nBuild) {
    if (blockIdx.x >= nBuild) {
        int i = (blockIdx.x - nBuild) * blockDim.x + threadIdx.x;
        const int S0 = 256 * 128, S1 = 256 * 256;
        if (i < S0)                 g_wtf[i] = __float2half_rn(W0[i]);
        if (i < S1) {
            g_wtf[S0 + i]      = __float2half_rn(W1[i]);
            g_wtf[S0 + S1 + i] = __float2half_rn(W2[i]);
        }
        return;
    }
    int gt = blockIdx.x * blockDim.x + threadIdx.x;
    int node = gt >> 5, lane = gt & 31;
    if (node >= n) return;
    float4 v;
    if (lane < 16) {
        v = reinterpret_cast<const float4*>(x + (size_t)node * 64)[lane];
    } else {
        int c = clab[batch[node]];
        v = reinterpret_cast<const float4*>(emb + (size_t)c * 64)[lane - 16];
    }
    __half2 h0 = __floats2half2_rn(v.x, v.y);
    __half2 h1 = __floats2half2_rn(v.z, v.w);
    *reinterpret_cast<uint2*>(g_in0 + (size_t)node * 128 + lane * 4) =
        make_uint2(*reinterpret_cast<uint32_t*>(&h0), *reinterpret_cast<uint32_t*>(&h1));
}

// ---------------- tensor-core GEMM + fused attention scores ------------------
#define SMSH (128 * 40)

template <int K, int SRC>
__global__ void __launch_bounds__(256, 2) gemm_tc_kernel(int woff, int M,
                                                         const float* __restrict__ asrc,
                                                         const float* __restrict__ adst) {
    constexpr int NT = K / 32;
    extern __shared__ __half smh[];
    const __half* __restrict__ A = (SRC == 0) ? g_in0 : g_out;
    const __half* __restrict__ Wm = g_wtf + woff;

    const int tid = threadIdx.x;
    const int warp = tid >> 5, lane = tid & 31;
    const int wm = warp >> 1;
    const int wn = warp & 1;
    const int g = lane >> 2, t4 = lane & 3;
    const int rowBase = blockIdx.x * 128;
    const int colBase = blockIdx.y * 128;

    const uint32_t sbase = (uint32_t)__cvta_generic_to_shared(smh);

    float4 c[2][8];
#pragma unroll
    for (int i = 0; i < 2; i++)
#pragma unroll
        for (int j = 0; j < 8; j++) c[i][j] = make_float4(0.f, 0.f, 0.f, 0.f);

    auto issue = [&](int t) {
        const int buf = t & 1;
        const int k0 = t * 32;
#pragma unroll
        for (int i = 0; i < 2; i++) {
            int f = tid + i * 256;
            int r = f >> 2, cc = (f & 3) * 8;
            int gr = rowBase + r;
            uint32_t da = sbase + (uint32_t)(buf * SMSH + r * 40 + cc) * 2u;
            cp16(da, A + (size_t)gr * K + k0 + cc, (gr < M) ? 16 : 0);
        }
#pragma unroll
        for (int i = 0; i < 2; i++) {
            int f = tid + i * 256;
            int r = f >> 2, cc = (f & 3) * 8;
            uint32_t db = sbase + (uint32_t)((2 + buf) * SMSH + r * 40 + cc) * 2u;
            cp16(db, Wm + (size_t)(colBase + r) * K + k0 + cc, 16);
        }
        asm volatile("cp.async.commit_group;\n" ::);
    };

    issue(0);

#pragma unroll 1
    for (int t = 0; t < NT; t++) {
        if (t + 1 < NT) {
            issue(t + 1);
            asm volatile("cp.async.wait_group 1;\n" ::);
        } else {
            asm volatile("cp.async.wait_group 0;\n" ::);
        }
        __syncthreads();
        const int buf = t & 1;
        const __half* Ab = smh + buf * SMSH;
        const __half* Bb = smh + (2 + buf) * SMSH;
#pragma unroll
        for (int ks = 0; ks < 2; ks++) {
            const int kb = ks * 16 + t4 * 2;
            uint32_t bfr[8][2];
#pragma unroll
            for (int j = 0; j < 8; j++) {
                int cn = wn * 64 + j * 8 + g;
                bfr[j][0] = *reinterpret_cast<const uint32_t*>(&Bb[cn * 40 + kb]);
                bfr[j][1] = *reinterpret_cast<const uint32_t*>(&Bb[cn * 40 + kb + 8]);
            }
            uint32_t afr[2][4];
#pragma unroll
            for (int i = 0; i < 2; i++) {
                int r = wm * 32 + i * 16 + g;
                afr[i][0] = *reinterpret_cast<const uint32_t*>(&Ab[r * 40 + kb]);
                afr[i][1] = *reinterpret_cast<const uint32_t*>(&Ab[(r + 8) * 40 + kb]);
                afr[i][2] = *reinterpret_cast<const uint32_t*>(&Ab[r * 40 + kb + 8]);
                afr[i][3] = *reinterpret_cast<const uint32_t*>(&Ab[(r + 8) * 40 + kb + 8]);
            }
#pragma unroll
            for (int i = 0; i < 2; i++)
#pragma unroll
                for (int j = 0; j < 8; j++) mma_f16(c[i][j], afr[i], bfr[j]);
        }
        __syncthreads();
    }

    // epilogue A: fp16 store to g_feat[M,256]
#pragma unroll
    for (int i = 0; i < 2; i++) {
#pragma unroll
        for (int j = 0; j < 8; j++) {
            int row0 = rowBase + wm * 32 + i * 16 + g;
            int coln = colBase + wn * 64 + j * 8 + 2 * t4;
            if (row0 < M)
                *reinterpret_cast<__half2*>(g_feat + (size_t)row0 * 256 + coln) =
                    __floats2half2_rn(c[i][j].x, c[i][j].y);
            if (row0 + 8 < M)
                *reinterpret_cast<__half2*>(g_feat + (size_t)(row0 + 8) * 256 + coln) =
                    __floats2half2_rn(c[i][j].z, c[i][j].w);
        }
    }

    // epilogue B: fused attention scores (warp's 64 cols == one head)
    {
        const int head = blockIdx.y * 2 + wn;
        const float* ah = asrc + head * 64;
        const float* dh = adst + head * 64;
        float ssp[4] = {0.f, 0.f, 0.f, 0.f}, sdp[4] = {0.f, 0.f, 0.f, 0.f};
#pragma unroll
        for (int j = 0; j < 8; j++) {
            int col = j * 8 + 2 * t4;
            float2 av = *reinterpret_cast<const float2*>(ah + col);
            float2 dv = *reinterpret_cast<const float2*>(dh + col);
#pragma unroll
            for (int i = 0; i < 2; i++) {
                ssp[i * 2]     += c[i][j].x * av.x + c[i][j].y * av.y;
                ssp[i * 2 + 1] += c[i][j].z * av.x + c[i][j].w * av.y;
                sdp[i * 2]     += c[i][j].x * dv.x + c[i][j].y * dv.y;
                sdp[i * 2 + 1] += c[i][j].z * dv.x + c[i][j].w * dv.y;
            }
        }
#pragma unroll
        for (int off = 1; off <= 2; off <<= 1) {
#pragma unroll
            for (int k = 0; k < 4; k++) {
                ssp[k] += __shfl_xor_sync(0xffffffffu, ssp[k], off);
                sdp[k] += __shfl_xor_sync(0xffffffffu, sdp[k], off);
            }
        }
        if (t4 == 0) {
#pragma unroll
            for (int k = 0; k < 4; k++) {
                int row = rowBase + wm * 32 + (k >> 1) * 16 + (k & 1) * 8 + g;
                if (row < M) {
                    g_ssrc[row * 4 + head] = ssp[k];
                    g_sdst[row * 4 + head] = sdp[k];
                }
            }
        }
    }
}

// ---------------- CSR build (atomic-free scatter via epos: R16) --------------
__global__ void deg_kernel(const int* __restrict__ ei, int E, int ET) {
    int e = blockIdx.x * blockDim.x + threadIdx.x;
    if (e >= ET) return;
    int s, d; edge_sd(ei, e, E, s, d);
    g_epos[e] = atomicAdd(&g_deg[d], 1);
}

__global__ void scan1_kernel(int n) {
    __shared__ int sh[512];
    int i = blockIdx.x * 512 + threadIdx.x;
    int v = (i < n) ? g_deg[i] : 0;
    sh[threadIdx.x] = v;
    __syncthreads();
#pragma unroll
    for (int off = 1; off < 512; off <<= 1) {
        int t = (threadIdx.x >= off) ? sh[threadIdx.x - off] : 0;
        __syncthreads();
        if (threadIdx.x >= off) sh[threadIdx.x] += t;
        __syncthreads();
    }
    if (i < n) g_rowptr[i] = sh[threadIdx.x] - v;
    if (threadIdx.x == 511) g_bsum[blockIdx.x] = sh[511];
}

__global__ void scan23_kernel(int nb, int n) {
    __shared__ int sh[512];
    int v = (threadIdx.x < nb) ? g_bsum[threadIdx.x] : 0;
    sh[threadIdx.x] = v;
    __syncthreads();
#pragma unroll
    for (int off = 1; off < 512; off <<= 1) {
        int t = (threadIdx.x >= off) ? sh[threadIdx.x - off] : 0;
        __syncthreads();
        if (threadIdx.x >= off) sh[threadIdx.x] += t;
        __syncthreads();
    }
    int bpre = (blockIdx.x > 0) ? sh[blockIdx.x - 1] : 0;
    int i = blockIdx.x * 512 + threadIdx.x;
    if (i < n) g_rowptr[i] += bpre;
    if (blockIdx.x == 0 && threadIdx.x == 0) g_rowptr[n] = sh[nb - 1];
}

__global__ void scatter_kernel(const int* __restrict__ ei, int E, int ET) {
    int e = blockIdx.x * blockDim.x + threadIdx.x;
    if (e >= ET) return;
    int s, d; edge_sd(ei, e, E, s, d);
    g_csrc[g_rowptr[d] + g_epos[e]] = s;
}

// ---------------- fused softmax + aggregation (+ classifier on last layer) ---
// R17: deferred normalization merges phases 2+3 — no weight caches, no den
// reduce (redundant per-lane den identical within each 8-lane head group).
template <bool LAST>
__global__ void agg_kernel(const float* __restrict__ b,
                           const float* __restrict__ clsW,
                           const float* __restrict__ clsb,
                           float* __restrict__ y, int n) {
    int gt = blockIdx.x * blockDim.x + threadIdx.x;
    int dst = gt >> 5, lane = gt & 31;
    if (dst >= n) return;
    const int beg = g_rowptr[dst], end = g_rowptr[dst + 1];
    const float4 sd4 = *reinterpret_cast<const float4*>(g_sdst + (size_t)dst * 4);

    // phase 1: segment max per head (lane-parallel over edges)
    const float NEG = __int_as_float(0xff800000);
    float4 mx = make_float4(NEG, NEG, NEG, NEG);
    for (int i = beg + lane; i < end; i += 32) {
        int s = g_csrc[i];
        float4 ss = *reinterpret_cast<const float4*>(g_ssrc + (size_t)s * 4);
        mx.x = fmaxf(mx.x, lrelu(ss.x + sd4.x, 0.2f));
        mx.y = fmaxf(mx.y, lrelu(ss.y + sd4.y, 0.2f));
        mx.z = fmaxf(mx.z, lrelu(ss.z + sd4.z, 0.2f));
        mx.w = fmaxf(mx.w, lrelu(ss.w + sd4.w, 0.2f));
    }
#pragma unroll
    for (int off = 16; off; off >>= 1) {
        mx.x = fmaxf(mx.x, __shfl_xor_sync(0xffffffffu, mx.x, off));
        mx.y = fmaxf(mx.y, __shfl_xor_sync(0xffffffffu, mx.y, off));
        mx.z = fmaxf(mx.z, __shfl_xor_sync(0xffffffffu, mx.z, off));
        mx.w = fmaxf(mx.w, __shfl_xor_sync(0xffffffffu, mx.w, off));
    }

    const int h = lane >> 3;
    float mh  = (h & 2) ? ((h & 1) ? mx.w : mx.z) : ((h & 1) ? mx.y : mx.x);
    float sdh = (h & 2) ? ((h & 1) ? sd4.w : sd4.z) : ((h & 1) ? sd4.y : sd4.x);

    // phase 2+3 merged: un-normalized accumulation + inline den, 2-edge unroll
    float den = 0.f;
    float2 acc[4];
#pragma unroll
    for (int j = 0; j < 4; j++) acc[j] = make_float2(0.f, 0.f);

    int i = beg;
    for (; i + 1 < end; i += 2) {
        int s0 = g_csrc[i], s1 = g_csrc[i + 1];
        float w0 = __expf(lrelu(g_ssrc[(size_t)s0 * 4 + h] + sdh, 0.2f) - mh);
        float w1 = __expf(lrelu(g_ssrc[(size_t)s1 * 4 + h] + sdh, 0.2f) - mh);
        den += w0 + w1;
        uint4 p0 = *reinterpret_cast<const uint4*>(g_feat + (size_t)s0 * 256 + lane * 8);
        uint4 p1 = *reinterpret_cast<const uint4*>(g_feat + (size_t)s1 * 256 + lane * 8);
        const __half2* q0 = reinterpret_cast<const __half2*>(&p0);
        const __half2* q1 = reinterpret_cast<const __half2*>(&p1);
#pragma unroll
        for (int j = 0; j < 4; j++) {
            float2 f0 = __half22float2(q0[j]);
            float2 f1 = __half22float2(q1[j]);
            acc[j].x += w0 * f0.x + w1 * f1.x;
            acc[j].y += w0 * f0.y + w1 * f1.y;
        }
    }
    if (i < end) {
        int s0 = g_csrc[i];
        float w0 = __expf(lrelu(g_ssrc[(size_t)s0 * 4 + h] + sdh, 0.2f) - mh);
        den += w0;
        uint4 p0 = *reinterpret_cast<const uint4*>(g_feat + (size_t)s0 * 256 + lane * 8);
        const __half2* q0 = reinterpret_cast<const __half2*>(&p0);
#pragma unroll
        for (int j = 0; j < 4; j++) {
            float2 f0 = __half22float2(q0[j]);
            acc[j].x += w0 * f0.x;
            acc[j].y += w0 * f0.y;
        }
    }

    const float invd = 1.f / (den + 1e-16f);   // identical across each head group

    const float4 b0 = reinterpret_cast<const float4*>(b)[lane * 2];
    const float4 b1 = reinterpret_cast<const float4*>(b)[lane * 2 + 1];
    float o[8];
    o[0] = lrelu(acc[0].x * invd + b0.x, 0.01f); o[1] = lrelu(acc[0].y * invd + b0.y, 0.01f);
    o[2] = lrelu(acc[1].x * invd + b0.z, 0.01f); o[3] = lrelu(acc[1].y * invd + b0.w, 0.01f);
    o[4] = lrelu(acc[2].x * invd + b1.x, 0.01f); o[5] = lrelu(acc[2].y * invd + b1.y, 0.01f);
    o[6] = lrelu(acc[3].x * invd + b1.z, 0.01f); o[7] = lrelu(acc[3].y * invd + b1.w, 0.01f);

    if (!LAST) {
        __half2 h0 = __floats2half2_rn(o[0], o[1]);
        __half2 h1 = __floats2half2_rn(o[2], o[3]);
        __half2 h2 = __floats2half2_rn(o[4], o[5]);
        __half2 h3 = __floats2half2_rn(o[6], o[7]);
        *reinterpret_cast<uint4*>(g_out + (size_t)dst * 256 + lane * 8) =
            make_uint4(*reinterpret_cast<uint32_t*>(&h0), *reinterpret_cast<uint32_t*>(&h1),
                       *reinterpret_cast<uint32_t*>(&h2), *reinterpret_cast<uint32_t*>(&h3));
    } else {
        const float4 w0 = reinterpret_cast<const float4*>(clsW)[lane * 2];
        const float4 w1 = reinterpret_cast<const float4*>(clsW)[lane * 2 + 1];
        float sum = o[0] * w0.x + o[1] * w0.y + o[2] * w0.z + o[3] * w0.w +
                    o[4] * w1.x + o[5] * w1.y + o[6] * w1.z + o[7] * w1.w;
#pragma unroll
        for (int off = 16; off; off >>= 1) sum += __shfl_xor_sync(0xffffffffu, sum, off);
        if (lane == 0) y[dst] = sum + clsb[0];
    }
}

static inline int cdiv(int a, int b) { return (a + b - 1) / b; }

extern "C" void kernel_launch(void* const* d_in, const int* in_sizes, int n_in,
                              void* d_out, int out_size) {
    const float* x     = (const float*)d_in[0];
    const int*   ei    = (const int*)d_in[1];
    const int*   batch = (const int*)d_in[2];
    const int*   clab  = (const int*)d_in[3];
    const float* emb   = (const float*)d_in[4];
    const float* W0    = (const float*)d_in[5];
    const float* as0   = (const float*)d_in[6];
    const float* ad0   = (const float*)d_in[7];
    const float* b0    = (const float*)d_in[8];
    const float* W1    = (const float*)d_in[9];
    const float* as1   = (const float*)d_in[10];
    const float* ad1   = (const float*)d_in[11];
    const float* b1    = (const float*)d_in[12];
    const float* W2    = (const float*)d_in[13];
    const float* as2   = (const float*)d_in[14];
    const float* ad2   = (const float*)d_in[15];
    const float* b2    = (const float*)d_in[16];
    const float* clsW  = (const float*)d_in[17];
    const float* clsb  = (const float*)d_in[18];

    int n  = in_sizes[0] / 64;   // 50000
    int E  = in_sizes[1] / 2;    // 800000
    int ET = E + n;

    const int T = 256;
    int buildBlocks = cdiv(n * 32, T);
    int aggBlocks = cdiv(n * 32, 128);
    int nb = cdiv(n, 512);
    const int smBytes = 4 * SMSH * sizeof(__half);   // 40960 (2-stage)

    static cudaStream_t s2 = nullptr;
    static cudaEvent_t evFork = nullptr, evJoin = nullptr;
    static void* degAddr = nullptr;
    if (!s2) {
        cudaFuncSetAttribute(gemm_tc_kernel<128, 0>,
                             cudaFuncAttributeMaxDynamicSharedMemorySize, smBytes);
        cudaFuncSetAttribute(gemm_tc_kernel<256, 1>,
                             cudaFuncAttributeMaxDynamicSharedMemorySize, smBytes);
        cudaStreamCreateWithFlags(&s2, cudaStreamNonBlocking);
        cudaEventCreateWithFlags(&evFork, cudaEventDisableTiming);
        cudaEventCreateWithFlags(&evJoin, cudaEventDisableTiming);
        cudaGetSymbolAddress(&degAddr, g_deg);
    }

    // fork: CSR build on s2, overlapped with in0+weights + gemm0
    cudaEventRecord(evFork, 0);
    cudaStreamWaitEvent(s2, evFork, 0);
    cudaMemsetAsync(degAddr, 0, n * sizeof(int), s2);
    deg_kernel<<<cdiv(ET, T), T, 0, s2>>>(ei, E, ET);
    scan1_kernel<<<nb, 512, 0, s2>>>(n);
    scan23_kernel<<<nb, 512, 0, s2>>>(nb, n);
    scatter_kernel<<<cdiv(ET, T), T, 0, s2>>>(ei, E, ET);
    cudaEventRecord(evJoin, s2);

    // main stream: feature pipeline (weight convert fused into build kernel)
    build_in0_kernel<<<buildBlocks + 256, T>>>(x, batch, clab, emb, W0, W1, W2, n, buildBlocks);

    dim3 gemm_grid(cdiv(n, 128), 2);
    const int WOFF[3] = {0, 256 * 128, 256 * 128 + 256 * 256};
    const float* asl[3] = {as0, as1, as2};
    const float* adl[3] = {ad0, ad1, ad2};
    const float* bl[3]  = {b0, b1, b2};
    float* y = (float*)d_out;

    for (int l = 0; l < 3; l++) {
        if (l == 0) gemm_tc_kernel<128, 0><<<gemm_grid, T, smBytes>>>(WOFF[0], n, asl[l], adl[l]);
        else        gemm_tc_kernel<256, 1><<<gemm_grid, T, smBytes>>>(WOFF[l], n, asl[l], adl[l]);

        if (l == 0) cudaStreamWaitEvent(0, evJoin, 0);   // join CSR before first agg

        if (l < 2) agg_kernel<false><<<aggBlocks, 128>>>(bl[l], nullptr, nullptr, nullptr, n);
        else       agg_kernel<true><<<aggBlocks, 128>>>(bl[l], clsW, clsb, y, n);
    }
}